// round 2
// baseline (speedup 1.0000x reference)
#include <cuda_runtime.h>
#include <cuda_bf16.h>

// Problem constants (fixed by setup_inputs)
#define BB 8
#define DD 32
#define NN 131072
#define KK 64
#define DP 33            // padded row (bank-conflict avoidance): slot 32 = count
#define IGNORE_IDX (-100)
#define DELTA_V 0.5f
#define DELTA_D 1.5f

// ---- scratch (allocation-free: __device__ globals) ----
__device__ float g_sum[BB * KK * DD];   // per-batch per-cluster feature sums
__device__ float g_cnt[BB * KK];        // per-batch per-cluster counts
__device__ float g_mu [BB * KK * DD];   // cluster means
__device__ float g_var[BB * KK];        // per-cluster hinged variance sums
__device__ float g_ninst[BB];
__device__ float g_ldist[BB];
__device__ float g_lreg [BB];

// ---------------------------------------------------------------------------
__global__ void k_zero() {
    int t = blockIdx.x * blockDim.x + threadIdx.x;
    int total = BB * KK * DD;                   // largest array
    if (t < total) g_sum[t] = 0.0f;
    if (t < BB * KK) { g_cnt[t] = 0.0f; g_var[t] = 0.0f; }
    if (t < BB) { g_ninst[t] = 0.0f; g_ldist[t] = 0.0f; g_lreg[t] = 0.0f; }
}

// ---------------------------------------------------------------------------
// Pass 1: segment sums + counts. Block-private shared accumulation, then
// global atomics once per block. grid = (BLKX, B).
__global__ void k_pass1(const float* __restrict__ emb,
                        const int*   __restrict__ cls,
                        const int*   __restrict__ inst) {
    __shared__ float s[KK * DP];   // s[k*DP + d] (d==32 -> count)
    const int b = blockIdx.y;

    for (int i = threadIdx.x; i < KK * DP; i += blockDim.x) s[i] = 0.0f;
    __syncthreads();

    const float* eb = emb + (size_t)b * DD * NN;
    const int*   cb = cls  + (size_t)b * NN;
    const int*   ib = inst + (size_t)b * NN;

    const int stride = gridDim.x * blockDim.x;
    for (int n = blockIdx.x * blockDim.x + threadIdx.x; n < NN; n += stride) {
        int c = cb[n];
        if (c == IGNORE_IDX) continue;
        int id = (c == 1) ? 0 : ib[n];          // merge class-1 into instance 0
        float* row = &s[id * DP];
        atomicAdd(&row[32], 1.0f);
        #pragma unroll
        for (int d = 0; d < DD; d++) {
            atomicAdd(&row[d], eb[(size_t)d * NN + n]);   // coalesced global read
        }
    }
    __syncthreads();

    for (int i = threadIdx.x; i < KK * DP; i += blockDim.x) {
        float v = s[i];
        int k = i / DP, d = i % DP;
        if (d < DD) atomicAdd(&g_sum[(b * KK + k) * DD + d], v);
        else if (v != 0.0f) atomicAdd(&g_cnt[b * KK + k], v);
    }
}

// ---------------------------------------------------------------------------
// Pass 2: means, present mask, n_inst, pairwise hinge (l_dist), l_reg.
// grid = B, block = 256.
__global__ void k_pass2() {
    const int b = blockIdx.x;
    const int tid = threadIdx.x;
    __shared__ float s_mu[KK * DP];       // padded means
    __shared__ float s_cnt[KK];
    __shared__ int   s_pres[KK];
    __shared__ float red0[256], red1[256], red2[256];

    if (tid < KK) {
        float c = g_cnt[b * KK + tid];
        s_cnt[tid] = c;
        s_pres[tid] = (c > 0.0f) ? 1 : 0;
    }
    __syncthreads();

    for (int i = tid; i < KK * DD; i += blockDim.x) {
        int k = i / DD, d = i % DD;
        float m = g_sum[b * KK * DD + i] / (s_cnt[k] + 1e-8f);
        g_mu[b * KK * DD + i] = m;
        s_mu[k * DP + d] = m;
    }
    __syncthreads();

    // partial sums: n_present, l_reg numerator, l_dist numerator
    float np = 0.0f, lreg = 0.0f, ldist = 0.0f;
    for (int k = tid; k < KK; k += blockDim.x) np += (float)s_pres[k];
    for (int i = tid; i < KK * DD; i += blockDim.x) {
        int k = i / DD, d = i % DD;
        if (s_pres[k]) lreg += fabsf(s_mu[k * DP + d]);
    }
    for (int p = tid; p < KK * KK; p += blockDim.x) {
        int i = p >> 6, j = p & 63;
        if (i != j && s_pres[i] && s_pres[j]) {
            float dsum = 0.0f;
            #pragma unroll
            for (int d = 0; d < DD; d++)
                dsum += fabsf(s_mu[i * DP + d] - s_mu[j * DP + d]);
            float h = fmaxf(2.0f * DELTA_D - dsum, 0.0f);
            ldist += h * h;
        }
    }
    red0[tid] = np; red1[tid] = lreg; red2[tid] = ldist;
    __syncthreads();
    for (int off = 128; off > 0; off >>= 1) {
        if (tid < off) {
            red0[tid] += red0[tid + off];
            red1[tid] += red1[tid + off];
            red2[tid] += red2[tid + off];
        }
        __syncthreads();
    }
    if (tid == 0) {
        float npres  = red0[0];
        float n_inst = fmaxf(npres, 1.0f);
        float npairs = npres * npres - npres;
        g_ninst[b] = n_inst;
        g_lreg[b]  = red1[0] / n_inst;
        g_ldist[b] = (npairs > 0.0f) ? red2[0] / fmaxf(npairs, 1.0f) : 0.0f;
    }
}

// ---------------------------------------------------------------------------
// Pass 3: per-point hinged L1 distance to own cluster mean -> per-cluster sum.
__global__ void k_pass3(const float* __restrict__ emb,
                        const int*   __restrict__ cls,
                        const int*   __restrict__ inst) {
    __shared__ float s_mu[KK * DP];
    __shared__ float s_var[KK];
    const int b = blockIdx.y;

    for (int i = threadIdx.x; i < KK * DD; i += blockDim.x) {
        int k = i / DD, d = i % DD;
        s_mu[k * DP + d] = g_mu[b * KK * DD + i];
    }
    if (threadIdx.x < KK) s_var[threadIdx.x] = 0.0f;
    __syncthreads();

    const float* eb = emb + (size_t)b * DD * NN;
    const int*   cb = cls  + (size_t)b * NN;
    const int*   ib = inst + (size_t)b * NN;

    const int stride = gridDim.x * blockDim.x;
    for (int n = blockIdx.x * blockDim.x + threadIdx.x; n < NN; n += stride) {
        int c = cb[n];
        if (c == IGNORE_IDX) continue;
        int id = (c == 1) ? 0 : ib[n];
        const float* mrow = &s_mu[id * DP];
        float acc = 0.0f;
        #pragma unroll
        for (int d = 0; d < DD; d++)
            acc += fabsf(eb[(size_t)d * NN + n] - mrow[d]);
        float h = fmaxf(acc - DELTA_V, 0.0f);
        atomicAdd(&s_var[id], h * h);
    }
    __syncthreads();
    if (threadIdx.x < KK) {
        float v = s_var[threadIdx.x];
        if (v != 0.0f) atomicAdd(&g_var[b * KK + threadIdx.x], v);
    }
}

// ---------------------------------------------------------------------------
// Pass 4: finalize 4 output scalars (means over batch).
__global__ void k_pass4(float* __restrict__ out, int out_size) {
    __shared__ float acc[4];
    if (threadIdx.x < 4) acc[threadIdx.x] = 0.0f;
    __syncthreads();
    // one thread per batch
    if (threadIdx.x < BB) {
        const int b = threadIdx.x;
        float lvar = 0.0f;
        for (int k = 0; k < KK; k++)
            lvar += g_var[b * KK + k] / (g_cnt[b * KK + k] + 1e-8f);
        lvar /= g_ninst[b];
        float lv = 1.0f   * lvar;        // PARAM_VAR
        float ld = 1.0f   * g_ldist[b];  // PARAM_DIST
        float lr = 0.001f * g_lreg[b];   // PARAM_REG
        float loss = lv + ld + lr;       // LOSS_WEIGHT = 1
        atomicAdd(&acc[0], loss / BB);
        atomicAdd(&acc[1], lv   / BB);
        atomicAdd(&acc[2], ld   / BB);
        atomicAdd(&acc[3], lr   / BB);
    }
    __syncthreads();
    if (threadIdx.x < 4 && threadIdx.x < out_size)
        out[threadIdx.x] = acc[threadIdx.x];
}

// ---------------------------------------------------------------------------
extern "C" void kernel_launch(void* const* d_in, const int* in_sizes, int n_in,
                              void* d_out, int out_size) {
    const float* emb  = (const float*)d_in[0];
    const int*   cls  = (const int*)  d_in[1];   // semantic_labels (int32 on device)
    const int*   inst = (const int*)  d_in[2];   // instance_labels
    float* out = (float*)d_out;

    (void)in_sizes; (void)n_in;

    k_zero<<<(BB * KK * DD + 255) / 256, 256>>>();

    dim3 grid1(128, BB);
    k_pass1<<<grid1, 256>>>(emb, cls, inst);

    k_pass2<<<BB, 256>>>();

    dim3 grid3(128, BB);
    k_pass3<<<grid3, 256>>>(emb, cls, inst);

    k_pass4<<<1, 64>>>(out, out_size);
}

// round 3
// speedup vs baseline: 1.2011x; 1.2011x over previous
#include <cuda_runtime.h>
#include <cuda_bf16.h>

// Problem constants (fixed by setup_inputs)
#define BB 8
#define DD 32
#define NN 131072
#define KK 64
#define DP 33            // padded row for [K][D] accumulators / means (+count slot)
#define TS 257           // tile stride: d-major tile, 257 mod 32 == 1 -> conflict-free column reads
#define NT 256           // points per chunk (== blockDim)
#define G1 64            // blocks per batch, pass1
#define IGNORE_IDX (-100)
#define DELTA_V 0.5f
#define DELTA_D 1.5f

// ---- scratch (allocation-free: __device__ globals) ----
__device__ float g_sum[BB * KK * DD];   // per-batch per-cluster feature sums
__device__ float g_cnt[BB * KK];        // per-batch per-cluster counts
__device__ float g_mu [BB * KK * DD];   // cluster means
__device__ float g_var[BB * KK];        // per-cluster hinged variance sums
__device__ float g_ninst[BB];
__device__ float g_ldist[BB];
__device__ float g_lreg [BB];

// ---------------------------------------------------------------------------
__global__ void k_zero() {
    int t = blockIdx.x * blockDim.x + threadIdx.x;
    int total = BB * KK * DD;
    if (t < total) g_sum[t] = 0.0f;
    if (t < BB * KK) { g_cnt[t] = 0.0f; g_var[t] = 0.0f; }
    if (t < BB) { g_ninst[t] = 0.0f; g_ldist[t] = 0.0f; g_lreg[t] = 0.0f; }
}

// ---------------------------------------------------------------------------
// Pass 1 (v2): warp-per-point segment sum via transposed smem tile.
// - tile staged d-major: s_tile[d*TS + n'], float4 coalesced fill, conflict-free
// - each warp owns 32 points/chunk; per point: one conflict-free 32-lane ATOMS
//   to consecutive addresses s_acc[id*DP + lane] (vs 33 conflicted atomics before)
// grid = (G1, BB), block = 256.
__global__ void __launch_bounds__(256) k_pass1(const float* __restrict__ emb,
                                               const int*   __restrict__ cls,
                                               const int*   __restrict__ inst) {
    __shared__ float s_tile[DD * TS];   // 32*257*4 = 32.9 KB
    __shared__ float s_acc[KK * DP];    // 8.4 KB  (slot 32 = count)
    __shared__ int   s_id[NT];

    const int b    = blockIdx.y;
    const int tid  = threadIdx.x;
    const int w    = tid >> 5;
    const int lane = tid & 31;

    for (int i = tid; i < KK * DP; i += 256) s_acc[i] = 0.0f;

    const float* eb = emb  + (size_t)b * DD * NN;
    const int*   cb = cls  + (size_t)b * NN;
    const int*   ib = inst + (size_t)b * NN;

    const int chunk_stride = gridDim.x * NT;
    for (int n0 = blockIdx.x * NT; n0 < NN; n0 += chunk_stride) {
        __syncthreads();   // previous chunk's readers done (also covers acc zero)

        // ids for this chunk (one per thread)
        {
            int c  = cb[n0 + tid];
            s_id[tid] = (c == IGNORE_IDX) ? -1 : ((c == 1) ? 0 : ib[n0 + tid]);
        }
        // fill tile d-major with float4 loads: i in [0, DD*NT/4)
        #pragma unroll
        for (int r = 0; r < (DD * NT / 4) / 256; r++) {
            int i  = r * 256 + tid;
            int d  = i >> 6;          // NT/4 = 64 float4 per d
            int n4 = i & 63;
            float4 v = ((const float4*)(eb + (size_t)d * NN + n0))[n4];
            float* dst = &s_tile[d * TS + n4 * 4];
            dst[0] = v.x; dst[1] = v.y; dst[2] = v.z; dst[3] = v.w;
        }
        __syncthreads();

        // warp w processes points [w*32, w*32+32)
        #pragma unroll 4
        for (int p = 0; p < 32; p++) {
            int n2 = (w << 5) + p;
            int id = s_id[n2];
            if (id < 0) continue;
            float val = s_tile[lane * TS + n2];          // conflict-free (TS%32==1)
            atomicAdd(&s_acc[id * DP + lane], val);      // consecutive -> conflict-free
            if (lane == 0) atomicAdd(&s_acc[id * DP + 32], 1.0f);
        }
    }
    __syncthreads();

    // flush block-private accumulator to global
    for (int i = tid; i < KK * DP; i += 256) {
        float v = s_acc[i];
        if (v != 0.0f) {
            int k = i / DP, d = i - k * DP;
            if (d < DD) atomicAdd(&g_sum[(b * KK + k) * DD + d], v);
            else        atomicAdd(&g_cnt[b * KK + k], v);
        }
    }
}

// ---------------------------------------------------------------------------
// Pass 2: means, present mask, n_inst, pairwise hinge (l_dist), l_reg.
// grid = B, block = 256.
__global__ void k_pass2() {
    const int b = blockIdx.x;
    const int tid = threadIdx.x;
    __shared__ float s_mu[KK * DP];
    __shared__ float s_cnt[KK];
    __shared__ int   s_pres[KK];
    __shared__ float red0[256], red1[256], red2[256];

    if (tid < KK) {
        float c = g_cnt[b * KK + tid];
        s_cnt[tid] = c;
        s_pres[tid] = (c > 0.0f) ? 1 : 0;
    }
    __syncthreads();

    for (int i = tid; i < KK * DD; i += blockDim.x) {
        int k = i / DD, d = i - k * DD;
        float m = g_sum[b * KK * DD + i] / (s_cnt[k] + 1e-8f);
        g_mu[b * KK * DD + i] = m;
        s_mu[k * DP + d] = m;
    }
    __syncthreads();

    float np = 0.0f, lreg = 0.0f, ldist = 0.0f;
    for (int k = tid; k < KK; k += blockDim.x) np += (float)s_pres[k];
    for (int i = tid; i < KK * DD; i += blockDim.x) {
        int k = i / DD, d = i - k * DD;
        if (s_pres[k]) lreg += fabsf(s_mu[k * DP + d]);
    }
    for (int p = tid; p < KK * KK; p += blockDim.x) {
        int i = p >> 6, j = p & 63;
        if (i != j && s_pres[i] && s_pres[j]) {
            float dsum = 0.0f;
            #pragma unroll
            for (int d = 0; d < DD; d++)
                dsum += fabsf(s_mu[i * DP + d] - s_mu[j * DP + d]);
            float h = fmaxf(2.0f * DELTA_D - dsum, 0.0f);
            ldist += h * h;
        }
    }
    red0[tid] = np; red1[tid] = lreg; red2[tid] = ldist;
    __syncthreads();
    for (int off = 128; off > 0; off >>= 1) {
        if (tid < off) {
            red0[tid] += red0[tid + off];
            red1[tid] += red1[tid + off];
            red2[tid] += red2[tid + off];
        }
        __syncthreads();
    }
    if (tid == 0) {
        float npres  = red0[0];
        float n_inst = fmaxf(npres, 1.0f);
        float npairs = npres * npres - npres;
        g_ninst[b] = n_inst;
        g_lreg[b]  = red1[0] / n_inst;
        g_ldist[b] = (npairs > 0.0f) ? red2[0] / fmaxf(npairs, 1.0f) : 0.0f;
    }
}

// ---------------------------------------------------------------------------
// Pass 3 (v2): float4 over n — 4 points/thread, 32 unrolled LDG.128 per group
// for high MLP. One shared atomic per point.
// grid = (NN/4/256, BB) = (128, 8), block = 256: exactly one group per thread.
__global__ void __launch_bounds__(256) k_pass3(const float* __restrict__ emb,
                                               const int*   __restrict__ cls,
                                               const int*   __restrict__ inst) {
    __shared__ float s_mu[KK * DP];
    __shared__ float s_var[KK];
    const int b = blockIdx.y;

    for (int i = threadIdx.x; i < KK * DD; i += blockDim.x) {
        int k = i / DD, d = i - k * DD;
        s_mu[k * DP + d] = g_mu[b * KK * DD + i];
    }
    if (threadIdx.x < KK) s_var[threadIdx.x] = 0.0f;
    __syncthreads();

    const float* eb = emb  + (size_t)b * DD * NN;
    const int*   cb = cls  + (size_t)b * NN;
    const int*   ib = inst + (size_t)b * NN;

    const int stride4 = gridDim.x * blockDim.x;
    for (int n4 = blockIdx.x * blockDim.x + threadIdx.x; n4 < NN / 4; n4 += stride4) {
        int4 c4 = ((const int4*)cb)[n4];
        int4 i4 = ((const int4*)ib)[n4];
        int id0 = (c4.x == IGNORE_IDX) ? -1 : ((c4.x == 1) ? 0 : i4.x);
        int id1 = (c4.y == IGNORE_IDX) ? -1 : ((c4.y == 1) ? 0 : i4.y);
        int id2 = (c4.z == IGNORE_IDX) ? -1 : ((c4.z == 1) ? 0 : i4.z);
        int id3 = (c4.w == IGNORE_IDX) ? -1 : ((c4.w == 1) ? 0 : i4.w);
        const float* m0 = &s_mu[(id0 < 0 ? 0 : id0) * DP];
        const float* m1 = &s_mu[(id1 < 0 ? 0 : id1) * DP];
        const float* m2 = &s_mu[(id2 < 0 ? 0 : id2) * DP];
        const float* m3 = &s_mu[(id3 < 0 ? 0 : id3) * DP];

        float a0 = 0.0f, a1 = 0.0f, a2 = 0.0f, a3 = 0.0f;
        #pragma unroll
        for (int d = 0; d < DD; d++) {
            float4 v = ((const float4*)(eb + (size_t)d * NN))[n4];
            a0 += fabsf(v.x - m0[d]);
            a1 += fabsf(v.y - m1[d]);
            a2 += fabsf(v.z - m2[d]);
            a3 += fabsf(v.w - m3[d]);
        }
        if (id0 >= 0) { float h = fmaxf(a0 - DELTA_V, 0.0f); atomicAdd(&s_var[id0], h * h); }
        if (id1 >= 0) { float h = fmaxf(a1 - DELTA_V, 0.0f); atomicAdd(&s_var[id1], h * h); }
        if (id2 >= 0) { float h = fmaxf(a2 - DELTA_V, 0.0f); atomicAdd(&s_var[id2], h * h); }
        if (id3 >= 0) { float h = fmaxf(a3 - DELTA_V, 0.0f); atomicAdd(&s_var[id3], h * h); }
    }
    __syncthreads();
    if (threadIdx.x < KK) {
        float v = s_var[threadIdx.x];
        if (v != 0.0f) atomicAdd(&g_var[b * KK + threadIdx.x], v);
    }
}

// ---------------------------------------------------------------------------
// Pass 4: finalize 4 output scalars (means over batch).
__global__ void k_pass4(float* __restrict__ out, int out_size) {
    __shared__ float acc[4];
    if (threadIdx.x < 4) acc[threadIdx.x] = 0.0f;
    __syncthreads();
    if (threadIdx.x < BB) {
        const int b = threadIdx.x;
        float lvar = 0.0f;
        for (int k = 0; k < KK; k++)
            lvar += g_var[b * KK + k] / (g_cnt[b * KK + k] + 1e-8f);
        lvar /= g_ninst[b];
        float lv = 1.0f   * lvar;        // PARAM_VAR
        float ld = 1.0f   * g_ldist[b];  // PARAM_DIST
        float lr = 0.001f * g_lreg[b];   // PARAM_REG
        float loss = lv + ld + lr;       // LOSS_WEIGHT = 1
        atomicAdd(&acc[0], loss / BB);
        atomicAdd(&acc[1], lv   / BB);
        atomicAdd(&acc[2], ld   / BB);
        atomicAdd(&acc[3], lr   / BB);
    }
    __syncthreads();
    if (threadIdx.x < 4 && threadIdx.x < out_size)
        out[threadIdx.x] = acc[threadIdx.x];
}

// ---------------------------------------------------------------------------
extern "C" void kernel_launch(void* const* d_in, const int* in_sizes, int n_in,
                              void* d_out, int out_size) {
    const float* emb  = (const float*)d_in[0];
    const int*   cls  = (const int*)  d_in[1];
    const int*   inst = (const int*)  d_in[2];
    float* out = (float*)d_out;

    (void)in_sizes; (void)n_in;

    k_zero<<<(BB * KK * DD + 255) / 256, 256>>>();

    dim3 grid1(G1, BB);
    k_pass1<<<grid1, 256>>>(emb, cls, inst);

    k_pass2<<<BB, 256>>>();

    dim3 grid3(NN / 4 / 256, BB);   // (128, 8)
    k_pass3<<<grid3, 256>>>(emb, cls, inst);

    k_pass4<<<1, 64>>>(out, out_size);
}